// round 6
// baseline (speedup 1.0000x reference)
#include <cuda_runtime.h>
#include <cstdint>

// ---------------------------------------------------------------------------
// BSplineBasis: out[N,60] = cubic B-spline basis of min-max-normalized x.
// <=4 of 60 outputs per row are nonzero (degree 3). HBM-store-bound (252MB).
//
// R6: persistent blocks (1024 blocks x 8 tiles). The 30720B smem tile is
// zeroed ONCE; each iteration re-zeros only the <=2 float4s the thread
// dirtied previously (TMA reads leave smem intact), scatters the new <=2,
// and one elected thread bulk-copies the contiguous tile to gmem.
// Per-thread STS drops 17 -> ~4 amortized; L1tex was the R5 bottleneck.
// ---------------------------------------------------------------------------

#define NUM_KNOTS 64
#define DEGREE 3
#define NBASIS (NUM_KNOTS - DEGREE - 1)   // 60
#define ROWS_PER_BLOCK 128
#define TILE_FLOATS (ROWS_PER_BLOCK * NBASIS)   // 7680 floats = 30720 B
#define NPART 256
#define GRID_BLOCKS 1024
// inv table layout: d=1 at [0,63), d=2 at [63,125), d=3 at [125,186)
#define INV1 0
#define INV2 63
#define INV3 125
#define INV_TOTAL 186

__device__ unsigned g_pmin[NPART];
__device__ unsigned g_pmax[NPART];

__device__ __forceinline__ unsigned fmap(float f) {
    unsigned u = __float_as_uint(f);
    return (u & 0x80000000u) ? ~u : (u | 0x80000000u);
}
__device__ __forceinline__ float funmap(unsigned u) {
    u = (u & 0x80000000u) ? (u & 0x7FFFFFFFu) : ~u;
    return __uint_as_float(u);
}

__global__ void __launch_bounds__(256)
minmax_partials_kernel(const float* __restrict__ x, int n) {
    int tid = blockIdx.x * blockDim.x + threadIdx.x;
    int stride = gridDim.x * blockDim.x;

    unsigned lmin = 0xFFFFFFFFu;
    unsigned lmax = 0x00000000u;

    int n4 = n >> 2;
    const float4* x4 = (const float4*)x;
    for (int i = tid; i < n4; i += stride) {
        float4 v = x4[i];
        unsigned a = fmap(v.x), b = fmap(v.y), c = fmap(v.z), d = fmap(v.w);
        lmin = min(lmin, min(min(a, b), min(c, d)));
        lmax = max(lmax, max(max(a, b), max(c, d)));
    }
    for (int i = (n4 << 2) + tid; i < n; i += stride) {
        unsigned a = fmap(x[i]);
        lmin = min(lmin, a);
        lmax = max(lmax, a);
    }

    #pragma unroll
    for (int off = 16; off > 0; off >>= 1) {
        lmin = min(lmin, __shfl_xor_sync(0xFFFFFFFFu, lmin, off));
        lmax = max(lmax, __shfl_xor_sync(0xFFFFFFFFu, lmax, off));
    }

    __shared__ unsigned smin[8], smax[8];
    int lane = threadIdx.x & 31;
    int wid  = threadIdx.x >> 5;
    if (lane == 0) { smin[wid] = lmin; smax[wid] = lmax; }
    __syncthreads();
    if (wid == 0) {
        lmin = (lane < 8) ? smin[lane] : 0xFFFFFFFFu;
        lmax = (lane < 8) ? smax[lane] : 0x00000000u;
        #pragma unroll
        for (int off = 4; off > 0; off >>= 1) {
            lmin = min(lmin, __shfl_xor_sync(0xFFFFFFFFu, lmin, off));
            lmax = max(lmax, __shfl_xor_sync(0xFFFFFFFFu, lmax, off));
        }
        if (lane == 0) {
            g_pmin[blockIdx.x] = lmin;
            g_pmax[blockIdx.x] = lmax;
        }
    }
}

__global__ void __launch_bounds__(ROWS_PER_BLOCK)
bspline_kernel(const float* __restrict__ x,
               const float* __restrict__ knots,
               float* __restrict__ out, int n) {
    __shared__ __align__(16) float tile[TILE_FLOATS];   // 30720 B
    __shared__ float t[NUM_KNOTS];
    __shared__ float inv[INV_TOTAL];
    __shared__ unsigned rmin[4], rmax[4];

    int tid = threadIdx.x;

    // ---- prologue: knots, reciprocal tables, min/max (once per block) ----
    if (tid < NUM_KNOTS) t[tid] = __ldg(&knots[tid]);

    for (int f = tid; f < INV_TOTAL; f += ROWS_PER_BLOCK) {
        int d, j;
        if (f < INV2)      { d = 1; j = f; }
        else if (f < INV3) { d = 2; j = f - INV2; }
        else               { d = 3; j = f - INV3; }
        float den = __ldg(&knots[j + d]) - __ldg(&knots[j]);
        inv[f] = (den > 0.0f) ? __fdiv_rn(1.0f, den) : 0.0f;
    }

    {
        unsigned a = min(g_pmin[tid], g_pmin[tid + 128]);
        unsigned b = max(g_pmax[tid], g_pmax[tid + 128]);
        #pragma unroll
        for (int off = 16; off > 0; off >>= 1) {
            a = min(a, __shfl_xor_sync(0xFFFFFFFFu, a, off));
            b = max(b, __shfl_xor_sync(0xFFFFFFFFu, b, off));
        }
        if ((tid & 31) == 0) { rmin[tid >> 5] = a; rmax[tid >> 5] = b; }
    }

    // Zero the tile ONCE (coalesced STS.128).
    float4* tile4 = (float4*)tile;
    #pragma unroll
    for (int q = 0; q < TILE_FLOATS / 4 / ROWS_PER_BLOCK; ++q)
        tile4[q * ROWS_PER_BLOCK + tid] = make_float4(0.f, 0.f, 0.f, 0.f);
    __syncthreads();

    unsigned bmin = min(min(rmin[0], rmin[1]), min(rmin[2], rmin[3]));
    unsigned bmax = max(max(rmax[0], rmax[1]), max(rmax[2], rmax[3]));
    float xmin = funmap(bmin);
    float xmax = funmap(bmax);
    // Bit-exact reference normalization denominator.
    float nden = __fadd_rn(__fsub_rn(xmax, xmin), 1e-8f);

    float4* myrow = (float4*)(tile + tid * NBASIS);
    int prev_q0 = 0, prev_r = 0;
    bool dirty = false;

    int n_tiles = (n + ROWS_PER_BLOCK - 1) / ROWS_PER_BLOCK;

    // ---- persistent tile loop (grid-strided) ----
    for (int tile_i = blockIdx.x, it = 0; tile_i < n_tiles;
         tile_i += gridDim.x, ++it) {

        if (it > 0) {
            // Previous TMA copy of THIS buffer must finish before we rewrite.
            if (tid == 0)
                asm volatile("cp.async.bulk.wait_group 0;" ::: "memory");
            __syncthreads();
        }

        // Re-zero only what we dirtied last iteration (rest is still zero).
        if (dirty) {
            myrow[prev_q0] = make_float4(0.f, 0.f, 0.f, 0.f);
            if (prev_r != 0) myrow[prev_q0 + 1] = make_float4(0.f, 0.f, 0.f, 0.f);
            dirty = false;
        }

        int row = tile_i * ROWS_PER_BLOCK + tid;
        if (row < n) {
            // Bit-exact reference normalization (feeds the half-open interval
            // tests; the max element rounds to 1.0f -> all-zero row).
            float xn = __fdiv_rn(__fsub_rn(x[row], xmin), nden);

            // Span search: analytic guess + exact fixup.
            int i = DEGREE + (int)(xn * (float)(NUM_KNOTS - 2 * DEGREE - 1));
            i = max(DEGREE, min(i, NUM_KNOTS - DEGREE - 2));
            while (i > DEGREE && xn < t[i]) --i;
            while (i < NUM_KNOTS - DEGREE - 2 && xn >= t[i + 1]) ++i;

            float seed = (xn >= t[i] && xn < t[i + 1]) ? 1.0f : 0.0f;

            // Divide-free Cox-de Boor recursion on the 4-wide active window.
            float Bcur[DEGREE + 1];
            Bcur[0] = seed;
            #pragma unroll
            for (int d = 1; d <= DEGREE; ++d) {
                const int base = (d == 1) ? INV1 : (d == 2) ? INV2 : INV3;
                float Bnew[DEGREE + 1];
                #pragma unroll
                for (int k = 0; k <= d; ++k) {
                    int j = i - d + k;
                    float L = (xn - t[j])         * inv[base + j];
                    float R = (t[j + d + 1] - xn) * inv[base + j + 1];
                    float bl = (k >= 1) ? Bcur[k - 1] : 0.0f;
                    float br = (k <= d - 1) ? Bcur[k] : 0.0f;
                    Bnew[k] = L * bl + R * br;
                }
                #pragma unroll
                for (int k = 0; k <= d; ++k) Bcur[k] = Bnew[k];
            }

            // Scatter the active window as 1-2 composed float4 stores.
            int c0 = i - DEGREE;          // [0, 56]
            int q0 = c0 >> 2;
            int r  = c0 & 3;
            float4 f0, f1;
            f0.x = (r == 0) ? Bcur[0] : 0.f;
            f0.y = (r == 0) ? Bcur[1] : (r == 1) ? Bcur[0] : 0.f;
            f0.z = (r == 0) ? Bcur[2] : (r == 1) ? Bcur[1] : (r == 2) ? Bcur[0] : 0.f;
            f0.w = (r == 0) ? Bcur[3] : (r == 1) ? Bcur[2] : (r == 2) ? Bcur[1] : Bcur[0];
            f1.x = (r == 1) ? Bcur[3] : (r == 2) ? Bcur[2] : (r == 3) ? Bcur[1] : 0.f;
            f1.y = (r == 2) ? Bcur[3] : (r == 3) ? Bcur[2] : 0.f;
            f1.z = (r == 3) ? Bcur[3] : 0.f;
            f1.w = 0.f;
            myrow[q0] = f0;
            if (r != 0) myrow[q0 + 1] = f1;
            prev_q0 = q0; prev_r = r; dirty = true;
        }

        // Generic-proxy smem writes -> visible to the async (TMA) proxy.
        asm volatile("fence.proxy.async.shared::cta;" ::: "memory");
        __syncthreads();

        if (tid == 0) {
            int rows_left = n - tile_i * ROWS_PER_BLOCK;
            int valid = (rows_left < ROWS_PER_BLOCK) ? rows_left : ROWS_PER_BLOCK;
            unsigned bytes = (unsigned)valid * (NBASIS * 4);   // multiple of 16
            float* gdst = out + (size_t)tile_i * TILE_FLOATS;
            unsigned saddr;
            asm volatile("{ .reg .u64 a; cvta.to.shared.u64 a, %1; cvt.u32.u64 %0, a; }"
                         : "=r"(saddr) : "l"(tile));
            asm volatile("cp.async.bulk.global.shared::cta.bulk_group [%0], [%1], %2;"
                         :: "l"(gdst), "r"(saddr), "r"(bytes) : "memory");
            asm volatile("cp.async.bulk.commit_group;" ::: "memory");
        }
    }

    // Drain before the block (and its smem) goes away.
    if (tid == 0)
        asm volatile("cp.async.bulk.wait_group 0;" ::: "memory");
    __syncthreads();
}

extern "C" void kernel_launch(void* const* d_in, const int* in_sizes, int n_in,
                              void* d_out, int out_size) {
    const float* x     = (const float*)d_in[0];
    const float* knots = (const float*)d_in[1];
    float* out = (float*)d_out;
    int n = in_sizes[0];   // N_ROWS (x is [N,1])

    minmax_partials_kernel<<<NPART, 256>>>(x, n);
    bspline_kernel<<<GRID_BLOCKS, ROWS_PER_BLOCK>>>(x, knots, out, n);
}

// round 7
// speedup vs baseline: 1.0087x; 1.0087x over previous
#include <cuda_runtime.h>
#include <cstdint>

// ---------------------------------------------------------------------------
// BSplineBasis: out[N,60] = cubic B-spline basis of min-max-normalized x.
// <=4 of 60 outputs per row are nonzero (degree 3). HBM-store-bound (252MB).
//
// R7: persistent blocks + DOUBLE-BUFFERED TMA bulk stores.
//  - Two 30720B smem tiles alternate; reuse waits only for the copy issued
//    two iterations ago (cp.async.bulk.wait_group 1) -> drain fully hidden.
//  - Tiles zeroed once; each iteration re-zeros only the <=2 float4s this
//    thread dirtied on that buffer last time (TMA reads leave smem intact).
//  - Divide-free Cox-de Boor via guarded reciprocal tables; normalization
//    division kept bit-exact (it feeds half-open interval tests; the max
//    element rounds to xn==1.0f -> all-zero row, matching the reference).
// ---------------------------------------------------------------------------

#define NUM_KNOTS 64
#define DEGREE 3
#define NBASIS (NUM_KNOTS - DEGREE - 1)   // 60
#define ROWS_PER_BLOCK 128
#define TILE_FLOATS (ROWS_PER_BLOCK * NBASIS)   // 7680 floats = 30720 B
#define NPART 256
#define GRID_BLOCKS (148 * 3)
// inv table layout: d=1 at [0,63), d=2 at [63,125), d=3 at [125,186)
#define INV1 0
#define INV2 63
#define INV3 125
#define INV_TOTAL 186
// dynamic smem: 2 tiles + knots + inv + rmin/rmax
#define SMEM_BYTES ((2 * TILE_FLOATS + NUM_KNOTS + INV_TOTAL + 8) * 4)

__device__ unsigned g_pmin[NPART];
__device__ unsigned g_pmax[NPART];

__device__ __forceinline__ unsigned fmap(float f) {
    unsigned u = __float_as_uint(f);
    return (u & 0x80000000u) ? ~u : (u | 0x80000000u);
}
__device__ __forceinline__ float funmap(unsigned u) {
    u = (u & 0x80000000u) ? (u & 0x7FFFFFFFu) : ~u;
    return __uint_as_float(u);
}

__global__ void __launch_bounds__(256)
minmax_partials_kernel(const float* __restrict__ x, int n) {
    int tid = blockIdx.x * blockDim.x + threadIdx.x;
    int stride = gridDim.x * blockDim.x;

    unsigned lmin = 0xFFFFFFFFu;
    unsigned lmax = 0x00000000u;

    int n4 = n >> 2;
    const float4* x4 = (const float4*)x;
    for (int i = tid; i < n4; i += stride) {
        float4 v = x4[i];
        unsigned a = fmap(v.x), b = fmap(v.y), c = fmap(v.z), d = fmap(v.w);
        lmin = min(lmin, min(min(a, b), min(c, d)));
        lmax = max(lmax, max(max(a, b), max(c, d)));
    }
    for (int i = (n4 << 2) + tid; i < n; i += stride) {
        unsigned a = fmap(x[i]);
        lmin = min(lmin, a);
        lmax = max(lmax, a);
    }

    #pragma unroll
    for (int off = 16; off > 0; off >>= 1) {
        lmin = min(lmin, __shfl_xor_sync(0xFFFFFFFFu, lmin, off));
        lmax = max(lmax, __shfl_xor_sync(0xFFFFFFFFu, lmax, off));
    }

    __shared__ unsigned smin[8], smax[8];
    int lane = threadIdx.x & 31;
    int wid  = threadIdx.x >> 5;
    if (lane == 0) { smin[wid] = lmin; smax[wid] = lmax; }
    __syncthreads();
    if (wid == 0) {
        lmin = (lane < 8) ? smin[lane] : 0xFFFFFFFFu;
        lmax = (lane < 8) ? smax[lane] : 0x00000000u;
        #pragma unroll
        for (int off = 4; off > 0; off >>= 1) {
            lmin = min(lmin, __shfl_xor_sync(0xFFFFFFFFu, lmin, off));
            lmax = max(lmax, __shfl_xor_sync(0xFFFFFFFFu, lmax, off));
        }
        if (lane == 0) {
            g_pmin[blockIdx.x] = lmin;
            g_pmax[blockIdx.x] = lmax;
        }
    }
}

__global__ void __launch_bounds__(ROWS_PER_BLOCK)
bspline_kernel(const float* __restrict__ x,
               const float* __restrict__ knots,
               float* __restrict__ out, int n) {
    extern __shared__ __align__(16) float smem[];
    float* tileA = smem;                         // 7680 floats
    float* tileB = tileA + TILE_FLOATS;          // 7680 floats
    float* t     = tileB + TILE_FLOATS;          // 64
    float* inv   = t + NUM_KNOTS;                // 186
    unsigned* rmin = (unsigned*)(inv + INV_TOTAL);
    unsigned* rmax = rmin + 4;

    int tid = threadIdx.x;

    // ---- prologue (once per block) ----
    if (tid < NUM_KNOTS) t[tid] = __ldg(&knots[tid]);

    for (int f = tid; f < INV_TOTAL; f += ROWS_PER_BLOCK) {
        int d, j;
        if (f < INV2)      { d = 1; j = f; }
        else if (f < INV3) { d = 2; j = f - INV2; }
        else               { d = 3; j = f - INV3; }
        float den = __ldg(&knots[j + d]) - __ldg(&knots[j]);
        inv[f] = (den > 0.0f) ? __fdiv_rn(1.0f, den) : 0.0f;
    }

    {
        unsigned a = min(g_pmin[tid], g_pmin[tid + 128]);
        unsigned b = max(g_pmax[tid], g_pmax[tid + 128]);
        #pragma unroll
        for (int off = 16; off > 0; off >>= 1) {
            a = min(a, __shfl_xor_sync(0xFFFFFFFFu, a, off));
            b = max(b, __shfl_xor_sync(0xFFFFFFFFu, b, off));
        }
        if ((tid & 31) == 0) { rmin[tid >> 5] = a; rmax[tid >> 5] = b; }
    }

    // Zero both tiles ONCE (coalesced STS.128).
    {
        float4* a4 = (float4*)tileA;
        float4* b4 = (float4*)tileB;
        #pragma unroll
        for (int q = 0; q < TILE_FLOATS / 4 / ROWS_PER_BLOCK; ++q) {
            a4[q * ROWS_PER_BLOCK + tid] = make_float4(0.f, 0.f, 0.f, 0.f);
            b4[q * ROWS_PER_BLOCK + tid] = make_float4(0.f, 0.f, 0.f, 0.f);
        }
    }
    __syncthreads();

    unsigned bmin = min(min(rmin[0], rmin[1]), min(rmin[2], rmin[3]));
    unsigned bmax = max(max(rmax[0], rmax[1]), max(rmax[2], rmax[3]));
    float xmin = funmap(bmin);
    float xmax = funmap(bmax);
    float nden = __fadd_rn(__fsub_rn(xmax, xmin), 1e-8f);

    float4* myrow[2];
    myrow[0] = (float4*)(tileA + tid * NBASIS);
    myrow[1] = (float4*)(tileB + tid * NBASIS);
    int  prev_q0[2] = {0, 0};
    int  prev_r[2]  = {0, 0};
    bool dirty[2]   = {false, false};

    int n_tiles = (n + ROWS_PER_BLOCK - 1) / ROWS_PER_BLOCK;

    // ---- persistent double-buffered tile loop ----
    for (int tile_i = blockIdx.x, it = 0; tile_i < n_tiles;
         tile_i += gridDim.x, ++it) {

        int buf = it & 1;
        float* tbuf = buf ? tileB : tileA;

        if (it >= 2) {
            // Wait only for the copy issued two iterations ago (this buffer);
            // the most recent copy (other buffer) stays in flight.
            if (tid == 0)
                asm volatile("cp.async.bulk.wait_group 1;" ::: "memory");
            __syncthreads();
        }

        // Re-zero what we dirtied on this buffer last time.
        if (dirty[buf]) {
            myrow[buf][prev_q0[buf]] = make_float4(0.f, 0.f, 0.f, 0.f);
            if (prev_r[buf] != 0)
                myrow[buf][prev_q0[buf] + 1] = make_float4(0.f, 0.f, 0.f, 0.f);
            dirty[buf] = false;
        }

        int row = tile_i * ROWS_PER_BLOCK + tid;
        if (row < n) {
            // Bit-exact reference normalization.
            float xn = __fdiv_rn(__fsub_rn(x[row], xmin), nden);

            // Span search: analytic guess + exact fixup.
            int i = DEGREE + (int)(xn * (float)(NUM_KNOTS - 2 * DEGREE - 1));
            i = max(DEGREE, min(i, NUM_KNOTS - DEGREE - 2));
            while (i > DEGREE && xn < t[i]) --i;
            while (i < NUM_KNOTS - DEGREE - 2 && xn >= t[i + 1]) ++i;

            float seed = (xn >= t[i] && xn < t[i + 1]) ? 1.0f : 0.0f;

            // Divide-free Cox-de Boor recursion (4-wide active window).
            float Bcur[DEGREE + 1];
            Bcur[0] = seed;
            #pragma unroll
            for (int d = 1; d <= DEGREE; ++d) {
                const int base = (d == 1) ? INV1 : (d == 2) ? INV2 : INV3;
                float Bnew[DEGREE + 1];
                #pragma unroll
                for (int k = 0; k <= d; ++k) {
                    int j = i - d + k;
                    float L = (xn - t[j])         * inv[base + j];
                    float R = (t[j + d + 1] - xn) * inv[base + j + 1];
                    float bl = (k >= 1) ? Bcur[k - 1] : 0.0f;
                    float br = (k <= d - 1) ? Bcur[k] : 0.0f;
                    Bnew[k] = L * bl + R * br;
                }
                #pragma unroll
                for (int k = 0; k <= d; ++k) Bcur[k] = Bnew[k];
            }

            // Scatter the active window as 1-2 composed float4 stores.
            int c0 = i - DEGREE;          // [0, 56]
            int q0 = c0 >> 2;
            int r  = c0 & 3;
            float4 f0, f1;
            f0.x = (r == 0) ? Bcur[0] : 0.f;
            f0.y = (r == 0) ? Bcur[1] : (r == 1) ? Bcur[0] : 0.f;
            f0.z = (r == 0) ? Bcur[2] : (r == 1) ? Bcur[1] : (r == 2) ? Bcur[0] : 0.f;
            f0.w = (r == 0) ? Bcur[3] : (r == 1) ? Bcur[2] : (r == 2) ? Bcur[1] : Bcur[0];
            f1.x = (r == 1) ? Bcur[3] : (r == 2) ? Bcur[2] : (r == 3) ? Bcur[1] : 0.f;
            f1.y = (r == 2) ? Bcur[3] : (r == 3) ? Bcur[2] : 0.f;
            f1.z = (r == 3) ? Bcur[3] : 0.f;
            f1.w = 0.f;
            myrow[buf][q0] = f0;
            if (r != 0) myrow[buf][q0 + 1] = f1;
            prev_q0[buf] = q0; prev_r[buf] = r; dirty[buf] = true;
        }

        // Generic-proxy smem writes -> visible to the async (TMA) proxy.
        asm volatile("fence.proxy.async.shared::cta;" ::: "memory");
        __syncthreads();

        if (tid == 0) {
            int rows_left = n - tile_i * ROWS_PER_BLOCK;
            int valid = (rows_left < ROWS_PER_BLOCK) ? rows_left : ROWS_PER_BLOCK;
            unsigned bytes = (unsigned)valid * (NBASIS * 4);   // multiple of 16
            float* gdst = out + (size_t)tile_i * TILE_FLOATS;
            unsigned saddr;
            asm volatile("{ .reg .u64 a; cvta.to.shared.u64 a, %1; cvt.u32.u64 %0, a; }"
                         : "=r"(saddr) : "l"(tbuf));
            asm volatile("cp.async.bulk.global.shared::cta.bulk_group [%0], [%1], %2;"
                         :: "l"(gdst), "r"(saddr), "r"(bytes) : "memory");
            asm volatile("cp.async.bulk.commit_group;" ::: "memory");
        }
    }

    // Drain before the block (and its smem) goes away.
    if (tid == 0)
        asm volatile("cp.async.bulk.wait_group 0;" ::: "memory");
    __syncthreads();
}

extern "C" void kernel_launch(void* const* d_in, const int* in_sizes, int n_in,
                              void* d_out, int out_size) {
    const float* x     = (const float*)d_in[0];
    const float* knots = (const float*)d_in[1];
    float* out = (float*)d_out;
    int n = in_sizes[0];   // N_ROWS (x is [N,1])

    // Attribute set (idempotent, not a stream op -> graph-capture safe).
    cudaFuncSetAttribute(bspline_kernel,
                         cudaFuncAttributeMaxDynamicSharedMemorySize, SMEM_BYTES);

    minmax_partials_kernel<<<NPART, 256>>>(x, n);
    bspline_kernel<<<GRID_BLOCKS, ROWS_PER_BLOCK, SMEM_BYTES>>>(x, knots, out, n);
}

// round 8
// speedup vs baseline: 1.0449x; 1.0359x over previous
#include <cuda_runtime.h>
#include <cstdint>

// ---------------------------------------------------------------------------
// BSplineBasis: out[N,60] = cubic B-spline basis of min-max-normalized x.
// <=4 of 60 outputs per row are nonzero (degree 3).
//
// R8: NO smem staging, NO TMA. Each warp owns 32 rows = exactly 480
// contiguous float4 of out:
//   1) 15 coalesced STG.128 zeros per lane cover the warp's whole span,
//   2) __syncwarp (fence) orders them against step 3,
//   3) each lane overwrites its own row's 1-2 aligned float4s with the
//      composed 4-value active window (merges with the zeros in L2).
// Tiny smem (knots + reciprocal tables) -> ~full occupancy, no block-wide
// syncs in the hot path, no TMA drain tail.
// ---------------------------------------------------------------------------

#define NUM_KNOTS 64
#define DEGREE 3
#define NBASIS (NUM_KNOTS - DEGREE - 1)   // 60
#define BLOCK_THREADS 256
#define NPART 256
// inv table layout: d=1 at [0,63), d=2 at [63,125), d=3 at [125,186)
#define INV1 0
#define INV2 63
#define INV3 125
#define INV_TOTAL 186

__device__ unsigned g_pmin[NPART];
__device__ unsigned g_pmax[NPART];

__device__ __forceinline__ unsigned fmap(float f) {
    unsigned u = __float_as_uint(f);
    return (u & 0x80000000u) ? ~u : (u | 0x80000000u);
}
__device__ __forceinline__ float funmap(unsigned u) {
    u = (u & 0x80000000u) ? (u & 0x7FFFFFFFu) : ~u;
    return __uint_as_float(u);
}

__global__ void __launch_bounds__(256)
minmax_partials_kernel(const float* __restrict__ x, int n) {
    int tid = blockIdx.x * blockDim.x + threadIdx.x;
    int stride = gridDim.x * blockDim.x;

    unsigned lmin = 0xFFFFFFFFu;
    unsigned lmax = 0x00000000u;

    int n4 = n >> 2;
    const float4* x4 = (const float4*)x;
    for (int i = tid; i < n4; i += stride) {
        float4 v = x4[i];
        unsigned a = fmap(v.x), b = fmap(v.y), c = fmap(v.z), d = fmap(v.w);
        lmin = min(lmin, min(min(a, b), min(c, d)));
        lmax = max(lmax, max(max(a, b), max(c, d)));
    }
    for (int i = (n4 << 2) + tid; i < n; i += stride) {
        unsigned a = fmap(x[i]);
        lmin = min(lmin, a);
        lmax = max(lmax, a);
    }

    #pragma unroll
    for (int off = 16; off > 0; off >>= 1) {
        lmin = min(lmin, __shfl_xor_sync(0xFFFFFFFFu, lmin, off));
        lmax = max(lmax, __shfl_xor_sync(0xFFFFFFFFu, lmax, off));
    }

    __shared__ unsigned smin[8], smax[8];
    int lane = threadIdx.x & 31;
    int wid  = threadIdx.x >> 5;
    if (lane == 0) { smin[wid] = lmin; smax[wid] = lmax; }
    __syncthreads();
    if (wid == 0) {
        lmin = (lane < 8) ? smin[lane] : 0xFFFFFFFFu;
        lmax = (lane < 8) ? smax[lane] : 0x00000000u;
        #pragma unroll
        for (int off = 4; off > 0; off >>= 1) {
            lmin = min(lmin, __shfl_xor_sync(0xFFFFFFFFu, lmin, off));
            lmax = max(lmax, __shfl_xor_sync(0xFFFFFFFFu, lmax, off));
        }
        if (lane == 0) {
            g_pmin[blockIdx.x] = lmin;
            g_pmax[blockIdx.x] = lmax;
        }
    }
}

__global__ void __launch_bounds__(BLOCK_THREADS)
bspline_kernel(const float* __restrict__ x,
               const float* __restrict__ knots,
               float* __restrict__ out, int n) {
    __shared__ float t[NUM_KNOTS];
    __shared__ float inv[INV_TOTAL];
    __shared__ unsigned rmin[8], rmax[8];

    int tid  = threadIdx.x;
    int lane = tid & 31;
    int wid  = tid >> 5;

    // ---- prologue: knots, reciprocal tables, min/max (1KB smem, 1 barrier) --
    if (tid < NUM_KNOTS) t[tid] = __ldg(&knots[tid]);

    for (int f = tid; f < INV_TOTAL; f += BLOCK_THREADS) {
        int d, j;
        if (f < INV2)      { d = 1; j = f; }
        else if (f < INV3) { d = 2; j = f - INV2; }
        else               { d = 3; j = f - INV3; }
        float den = __ldg(&knots[j + d]) - __ldg(&knots[j]);
        inv[f] = (den > 0.0f) ? __fdiv_rn(1.0f, den) : 0.0f;
    }

    {
        unsigned a = g_pmin[tid & (NPART - 1)];
        unsigned b = g_pmax[tid & (NPART - 1)];
        #pragma unroll
        for (int off = 16; off > 0; off >>= 1) {
            a = min(a, __shfl_xor_sync(0xFFFFFFFFu, a, off));
            b = max(b, __shfl_xor_sync(0xFFFFFFFFu, b, off));
        }
        if (lane == 0) { rmin[wid] = a; rmax[wid] = b; }
    }
    __syncthreads();

    unsigned bmin = 0xFFFFFFFFu, bmax = 0u;
    #pragma unroll
    for (int w = 0; w < 8; ++w) {
        bmin = min(bmin, rmin[w]);
        bmax = max(bmax, rmax[w]);
    }
    float xmin = funmap(bmin);
    float xmax = funmap(bmax);
    // Bit-exact reference normalization denominator.
    float nden = __fadd_rn(__fsub_rn(xmax, xmin), 1e-8f);

    int row = blockIdx.x * BLOCK_THREADS + tid;
    bool active = (row < n);

    float Bcur[DEGREE + 1] = {0.f, 0.f, 0.f, 0.f};
    int c0 = 0;

    if (active) {
        // Bit-exact normalization (feeds half-open interval tests; max
        // element rounds to xn==1.0f -> all-zero row, like the reference).
        float xn = __fdiv_rn(__fsub_rn(x[row], xmin), nden);

        // Span search: analytic guess + exact fixup.
        int i = DEGREE + (int)(xn * (float)(NUM_KNOTS - 2 * DEGREE - 1));
        i = max(DEGREE, min(i, NUM_KNOTS - DEGREE - 2));
        while (i > DEGREE && xn < t[i]) --i;
        while (i < NUM_KNOTS - DEGREE - 2 && xn >= t[i + 1]) ++i;

        float seed = (xn >= t[i] && xn < t[i + 1]) ? 1.0f : 0.0f;

        // Divide-free Cox-de Boor recursion on the 4-wide active window.
        Bcur[0] = seed;
        #pragma unroll
        for (int d = 1; d <= DEGREE; ++d) {
            const int base = (d == 1) ? INV1 : (d == 2) ? INV2 : INV3;
            float Bnew[DEGREE + 1];
            #pragma unroll
            for (int k = 0; k <= d; ++k) {
                int j = i - d + k;
                float L = (xn - t[j])         * inv[base + j];
                float R = (t[j + d + 1] - xn) * inv[base + j + 1];
                float bl = (k >= 1) ? Bcur[k - 1] : 0.0f;
                float br = (k <= d - 1) ? Bcur[k] : 0.0f;
                Bnew[k] = L * bl + R * br;
            }
            #pragma unroll
            for (int k = 0; k <= d; ++k) Bcur[k] = Bnew[k];
        }
        c0 = i - DEGREE;   // [0, 56]
    }

    // ---- Phase 1: warp-cooperative coalesced zeroing of the warp's span ----
    // Warp owns rows [wrow0, wrow0+32) = 480 contiguous float4 of out.
    int wrow0 = blockIdx.x * BLOCK_THREADS + (wid << 5);
    float4* ospan = (float4*)(out + (size_t)wrow0 * NBASIS);
    const float4 z4 = make_float4(0.f, 0.f, 0.f, 0.f);

    if (wrow0 + 32 <= n) {
        #pragma unroll
        for (int s = 0; s < 15; ++s)
            ospan[s * 32 + lane] = z4;
    } else if (wrow0 < n) {
        int valid4 = (n - wrow0) * (NBASIS / 4);
        for (int q = lane; q < valid4; q += 32)
            ospan[q] = z4;
    }

    // Order phase-1 stores (other lanes') before phase-2 overwrites.
    __syncwarp();

    // ---- Phase 2: composed overwrite of this row's 1-2 aligned float4s ----
    if (active) {
        int q0 = c0 >> 2;
        int r  = c0 & 3;
        float4 f0, f1;
        f0.x = (r == 0) ? Bcur[0] : 0.f;
        f0.y = (r == 0) ? Bcur[1] : (r == 1) ? Bcur[0] : 0.f;
        f0.z = (r == 0) ? Bcur[2] : (r == 1) ? Bcur[1] : (r == 2) ? Bcur[0] : 0.f;
        f0.w = (r == 0) ? Bcur[3] : (r == 1) ? Bcur[2] : (r == 2) ? Bcur[1] : Bcur[0];
        f1.x = (r == 1) ? Bcur[3] : (r == 2) ? Bcur[2] : (r == 3) ? Bcur[1] : 0.f;
        f1.y = (r == 2) ? Bcur[3] : (r == 3) ? Bcur[2] : 0.f;
        f1.z = (r == 3) ? Bcur[3] : 0.f;
        f1.w = 0.f;

        float4* myrow = (float4*)(out + (size_t)row * NBASIS);
        myrow[q0] = f0;
        if (r != 0) myrow[q0 + 1] = f1;   // r>0 implies q0+1 <= 14
    }
}

extern "C" void kernel_launch(void* const* d_in, const int* in_sizes, int n_in,
                              void* d_out, int out_size) {
    const float* x     = (const float*)d_in[0];
    const float* knots = (const float*)d_in[1];
    float* out = (float*)d_out;
    int n = in_sizes[0];   // N_ROWS (x is [N,1])

    minmax_partials_kernel<<<NPART, 256>>>(x, n);

    int blocks = (n + BLOCK_THREADS - 1) / BLOCK_THREADS;
    bspline_kernel<<<blocks, BLOCK_THREADS>>>(x, knots, out, n);
}

// round 9
// speedup vs baseline: 1.0954x; 1.0484x over previous
#include <cuda_runtime.h>
#include <cstdint>

// ---------------------------------------------------------------------------
// BSplineBasis: out[N,60] = cubic B-spline basis of min-max-normalized x.
// <=4 of 60 outputs per row are nonzero (degree 3). Output = 252MB, so the
// kernel is HBM-store-bound; the design goal is ONE coalesced write pass at
// the minimum possible L1 wavefront count (60 per warp per 32 rows).
//
// R9: each thread composes its row's active window into two float4s (f0,f1)
// + window index q0, staged in 36B of smem. The warp then writes its 32 rows
// (480 contiguous float4) in a single coalesced sweep, selecting f0/f1/zero
// per float4. No zero pre-pass, no scatter stores, no TMA, no big tile.
// ---------------------------------------------------------------------------

#define NUM_KNOTS 64
#define DEGREE 3
#define NBASIS (NUM_KNOTS - DEGREE - 1)   // 60
#define ROW_VEC4 (NBASIS / 4)             // 15 float4 per row
#define BLOCK_THREADS 256
#define NPART 256
// inv table layout: d=1 at [0,63), d=2 at [63,125), d=3 at [125,186)
#define INV1 0
#define INV2 63
#define INV3 125
#define INV_TOTAL 186

__device__ unsigned g_pmin[NPART];
__device__ unsigned g_pmax[NPART];

__device__ __forceinline__ unsigned fmap(float f) {
    unsigned u = __float_as_uint(f);
    return (u & 0x80000000u) ? ~u : (u | 0x80000000u);
}
__device__ __forceinline__ float funmap(unsigned u) {
    u = (u & 0x80000000u) ? (u & 0x7FFFFFFFu) : ~u;
    return __uint_as_float(u);
}

__global__ void __launch_bounds__(256)
minmax_partials_kernel(const float* __restrict__ x, int n) {
    int tid = blockIdx.x * blockDim.x + threadIdx.x;
    int stride = gridDim.x * blockDim.x;

    unsigned lmin = 0xFFFFFFFFu;
    unsigned lmax = 0x00000000u;

    int n4 = n >> 2;
    const float4* x4 = (const float4*)x;
    for (int i = tid; i < n4; i += stride) {
        float4 v = x4[i];
        unsigned a = fmap(v.x), b = fmap(v.y), c = fmap(v.z), d = fmap(v.w);
        lmin = min(lmin, min(min(a, b), min(c, d)));
        lmax = max(lmax, max(max(a, b), max(c, d)));
    }
    for (int i = (n4 << 2) + tid; i < n; i += stride) {
        unsigned a = fmap(x[i]);
        lmin = min(lmin, a);
        lmax = max(lmax, a);
    }

    #pragma unroll
    for (int off = 16; off > 0; off >>= 1) {
        lmin = min(lmin, __shfl_xor_sync(0xFFFFFFFFu, lmin, off));
        lmax = max(lmax, __shfl_xor_sync(0xFFFFFFFFu, lmax, off));
    }

    __shared__ unsigned smin[8], smax[8];
    int lane = threadIdx.x & 31;
    int wid  = threadIdx.x >> 5;
    if (lane == 0) { smin[wid] = lmin; smax[wid] = lmax; }
    __syncthreads();
    if (wid == 0) {
        lmin = (lane < 8) ? smin[lane] : 0xFFFFFFFFu;
        lmax = (lane < 8) ? smax[lane] : 0x00000000u;
        #pragma unroll
        for (int off = 4; off > 0; off >>= 1) {
            lmin = min(lmin, __shfl_xor_sync(0xFFFFFFFFu, lmin, off));
            lmax = max(lmax, __shfl_xor_sync(0xFFFFFFFFu, lmax, off));
        }
        if (lane == 0) {
            g_pmin[blockIdx.x] = lmin;
            g_pmax[blockIdx.x] = lmax;
        }
    }
}

__global__ void __launch_bounds__(BLOCK_THREADS)
bspline_kernel(const float* __restrict__ x,
               const float* __restrict__ knots,
               float* __restrict__ out, int n) {
    __shared__ float t[NUM_KNOTS];
    __shared__ float inv[INV_TOTAL];
    __shared__ unsigned rmin[8], rmax[8];
    __shared__ __align__(16) float4 sf0[BLOCK_THREADS];
    __shared__ __align__(16) float4 sf1[BLOCK_THREADS];
    __shared__ int sq0[BLOCK_THREADS];

    int tid  = threadIdx.x;
    int lane = tid & 31;
    int wid  = tid >> 5;

    // ---- prologue: knots, reciprocal tables, min/max ----
    if (tid < NUM_KNOTS) t[tid] = __ldg(&knots[tid]);

    for (int f = tid; f < INV_TOTAL; f += BLOCK_THREADS) {
        int d, j;
        if (f < INV2)      { d = 1; j = f; }
        else if (f < INV3) { d = 2; j = f - INV2; }
        else               { d = 3; j = f - INV3; }
        float den = __ldg(&knots[j + d]) - __ldg(&knots[j]);
        inv[f] = (den > 0.0f) ? __fdiv_rn(1.0f, den) : 0.0f;
    }

    {
        unsigned a = g_pmin[tid & (NPART - 1)];
        unsigned b = g_pmax[tid & (NPART - 1)];
        #pragma unroll
        for (int off = 16; off > 0; off >>= 1) {
            a = min(a, __shfl_xor_sync(0xFFFFFFFFu, a, off));
            b = max(b, __shfl_xor_sync(0xFFFFFFFFu, b, off));
        }
        if (lane == 0) { rmin[wid] = a; rmax[wid] = b; }
    }
    __syncthreads();

    unsigned bmin = 0xFFFFFFFFu, bmax = 0u;
    #pragma unroll
    for (int w = 0; w < 8; ++w) {
        bmin = min(bmin, rmin[w]);
        bmax = max(bmax, rmax[w]);
    }
    float xmin = funmap(bmin);
    float xmax = funmap(bmax);
    float nden = __fadd_rn(__fsub_rn(xmax, xmin), 1e-8f);

    int row = blockIdx.x * BLOCK_THREADS + tid;

    // ---- compute this thread's row: active window (f0, f1, q0) ----
    float4 f0 = make_float4(0.f, 0.f, 0.f, 0.f);
    float4 f1 = make_float4(0.f, 0.f, 0.f, 0.f);
    int q0 = -2;   // never matches for inactive rows

    if (row < n) {
        // Bit-exact reference normalization (feeds the half-open interval
        // tests; the max element rounds to xn==1.0f -> all-zero row).
        float xn = __fdiv_rn(__fsub_rn(x[row], xmin), nden);

        // Span search: analytic guess + exact fixup.
        int i = DEGREE + (int)(xn * (float)(NUM_KNOTS - 2 * DEGREE - 1));
        i = max(DEGREE, min(i, NUM_KNOTS - DEGREE - 2));
        while (i > DEGREE && xn < t[i]) --i;
        while (i < NUM_KNOTS - DEGREE - 2 && xn >= t[i + 1]) ++i;

        float seed = (xn >= t[i] && xn < t[i + 1]) ? 1.0f : 0.0f;

        // Divide-free Cox-de Boor recursion on the 4-wide active window.
        float Bcur[DEGREE + 1];
        Bcur[0] = seed;
        #pragma unroll
        for (int d = 1; d <= DEGREE; ++d) {
            const int base = (d == 1) ? INV1 : (d == 2) ? INV2 : INV3;
            float Bnew[DEGREE + 1];
            #pragma unroll
            for (int k = 0; k <= d; ++k) {
                int j = i - d + k;
                float L = (xn - t[j])         * inv[base + j];
                float R = (t[j + d + 1] - xn) * inv[base + j + 1];
                float bl = (k >= 1) ? Bcur[k - 1] : 0.0f;
                float br = (k <= d - 1) ? Bcur[k] : 0.0f;
                Bnew[k] = L * bl + R * br;
            }
            #pragma unroll
            for (int k = 0; k <= d; ++k) Bcur[k] = Bnew[k];
        }

        int c0 = i - DEGREE;          // [0, 56]
        q0 = c0 >> 2;                 // [0, 14]
        int r = c0 & 3;
        // f1 is all-zero when r==0 by construction.
        f0.x = (r == 0) ? Bcur[0] : 0.f;
        f0.y = (r == 0) ? Bcur[1] : (r == 1) ? Bcur[0] : 0.f;
        f0.z = (r == 0) ? Bcur[2] : (r == 1) ? Bcur[1] : (r == 2) ? Bcur[0] : 0.f;
        f0.w = (r == 0) ? Bcur[3] : (r == 1) ? Bcur[2] : (r == 2) ? Bcur[1] : Bcur[0];
        f1.x = (r == 1) ? Bcur[3] : (r == 2) ? Bcur[2] : (r == 3) ? Bcur[1] : 0.f;
        f1.y = (r == 2) ? Bcur[3] : (r == 3) ? Bcur[2] : 0.f;
        f1.z = (r == 3) ? Bcur[3] : 0.f;
        f1.w = 0.f;
    }

    // Stage the compact row descriptor (36B) in smem.
    sf0[tid] = f0;
    sf1[tid] = f1;
    sq0[tid] = q0;
    __syncwarp();    // consumers are warp-local only

    // ---- single coalesced write sweep: warp's 32 rows = 480 float4 ----
    int wrow0 = blockIdx.x * BLOCK_THREADS + (wid << 5);
    float4* ospan = (float4*)(out + (size_t)wrow0 * NBASIS);
    const int sbase = wid << 5;
    const float4 z4 = make_float4(0.f, 0.f, 0.f, 0.f);

    if (wrow0 + 32 <= n) {
        #pragma unroll
        for (int s = 0; s < ROW_VEC4; ++s) {
            int idx = s * 32 + lane;          // [0, 480)
            int src = idx / ROW_VEC4;         // owning local row [0, 32)
            int q   = idx - src * ROW_VEC4;   // float4 index within row
            int ss  = sbase + src;
            int q0s = sq0[ss];
            float4 v = (q == q0s) ? sf0[ss] : (q == q0s + 1) ? sf1[ss] : z4;
            ospan[idx] = v;
        }
    } else if (wrow0 < n) {
        int valid4 = (n - wrow0) * ROW_VEC4;
        for (int idx = lane; idx < valid4; idx += 32) {
            int src = idx / ROW_VEC4;
            int q   = idx - src * ROW_VEC4;
            int ss  = sbase + src;
            int q0s = sq0[ss];
            float4 v = (q == q0s) ? sf0[ss] : (q == q0s + 1) ? sf1[ss] : z4;
            ospan[idx] = v;
        }
    }
}

extern "C" void kernel_launch(void* const* d_in, const int* in_sizes, int n_in,
                              void* d_out, int out_size) {
    const float* x     = (const float*)d_in[0];
    const float* knots = (const float*)d_in[1];
    float* out = (float*)d_out;
    int n = in_sizes[0];   // N_ROWS (x is [N,1])

    minmax_partials_kernel<<<NPART, 256>>>(x, n);

    int blocks = (n + BLOCK_THREADS - 1) / BLOCK_THREADS;
    bspline_kernel<<<blocks, BLOCK_THREADS>>>(x, knots, out, n);
}